// round 15
// baseline (speedup 1.0000x reference)
#include <cuda_runtime.h>
#include <cuda_bf16.h>
#include <cstdint>

#define KCODES   1024
#define DIM      64
#define C1_MARG  8e-5f
#define SBASE    0x3E800000u     // bits of 0.25f

// ---------- device scratch (static, no allocation) ----------
__device__ float g_e[KCODES];                        // exact ref-chain enorms
__device__ __align__(16) float g_c0[KCODES];         // 0.5 + enorm
__device__ __align__(16) __nv_bfloat16 g_bpk[KCODES * DIM]; // (-2e) bf16 hi
__device__ unsigned g_b2hi_u;   // max_k ||(-2e)_hi||  (monotone, replay-idempotent)
__device__ unsigned g_b2lo_u;   // max_k ||(-2e)_lo||
__device__ int   g_flag[65536];
__device__ int   g_nflag;
__device__ int   g_done;
__device__ float g_loss;

__device__ __forceinline__ uint32_t smem_u32(const void* p) {
    uint32_t a;
    asm("{ .reg .u64 t; cvta.to.shared.u64 t, %1; cvt.u32.u64 %0, t; }"
        : "=r"(a) : "l"(p));
    return a;
}
__device__ __forceinline__ void ldsm4(uint32_t* r, uint32_t a) {
    asm volatile("ldmatrix.sync.aligned.m8n8.x4.shared.b16 {%0,%1,%2,%3}, [%4];"
        : "=r"(r[0]), "=r"(r[1]), "=r"(r[2]), "=r"(r[3]) : "r"(a));
}
__device__ __forceinline__ void mma_bf16(float* d, const uint32_t* a,
                                         uint32_t b0, uint32_t b1) {
    asm volatile(
        "mma.sync.aligned.m16n8k16.row.col.f32.bf16.bf16.f32 "
        "{%0,%1,%2,%3}, {%4,%5,%6,%7}, {%8,%9}, {%0,%1,%2,%3};"
        : "+f"(d[0]), "+f"(d[1]), "+f"(d[2]), "+f"(d[3])
        : "r"(a[0]), "r"(a[1]), "r"(a[2]), "r"(a[3]), "r"(b0), "r"(b1));
}
__device__ __forceinline__ void cpasync16(uint32_t sdst, const void* gsrc) {
    asm volatile("cp.async.cg.shared.global [%0], [%1], 16;"
                 :: "r"(sdst), "l"(gsrc) : "memory");
}

// ============ prep: exact enorm chain + bf16 B + norm bounds ============
__global__ void vq_prep(const float* __restrict__ cb) {
    int k = blockIdx.x * 128 + threadIdx.x;
    if (k == 0) { g_loss = 0.0f; g_nflag = 0; g_done = 0; }
    if (k < KCODES) {
        const float4* p4 = (const float4*)(cb + k * DIM);
        __nv_bfloat16* row = g_bpk + k * DIM;
        float s = 0.0f, h2 = 0.0f, l2 = 0.0f;
        #pragma unroll
        for (int q = 0; q < 16; ++q) {
            float4 v = p4[q];
            float e0 = v.x, e1 = v.y, e2 = v.z, e3 = v.w;
            s = __fadd_rn(s, __fmul_rn(e0, e0));
            s = __fadd_rn(s, __fmul_rn(e1, e1));
            s = __fadd_rn(s, __fmul_rn(e2, e2));
            s = __fadd_rn(s, __fmul_rn(e3, e3));
            float m0 = -2.0f * e0, m1 = -2.0f * e1, m2 = -2.0f * e2, m3 = -2.0f * e3;
            __nv_bfloat162 h01, h23;
            h01.x = __float2bfloat16(m0); h01.y = __float2bfloat16(m1);
            h23.x = __float2bfloat16(m2); h23.y = __float2bfloat16(m3);
            float f0 = __bfloat162float(h01.x), f1 = __bfloat162float(h01.y);
            float f2 = __bfloat162float(h23.x), f3 = __bfloat162float(h23.y);
            h2 += f0 * f0 + f1 * f1 + f2 * f2 + f3 * f3;
            float l0 = m0 - f0, l1 = m1 - f1, l2v = m2 - f2, l3 = m3 - f3;
            l2 += l0 * l0 + l1 * l1 + l2v * l2v + l3 * l3;
            *(__nv_bfloat162*)(row + q * 4)     = h01;
            *(__nv_bfloat162*)(row + q * 4 + 2) = h23;
        }
        g_e[k] = s;
        g_c0[k] = 0.5f + s;
        atomicMax(&g_b2hi_u, __float_as_uint(sqrtf(h2)));
        atomicMax(&g_b2lo_u, __float_as_uint(sqrtf(l2)));
    }
}

// ============ stage 1: 4-step HMMA + dynamic margin + fused output ============
#define ASTRIDE  144        // 9x16B rows -> conflict-free ldmatrix
#define SA       0          // 128*144 = 18432
#define SB       18432      // 2 stages x 64*144 = 9216
#define SBSTG    9216
#define SC0      36864      // 2 stages x 64 floats
#define SW       37376      // float[128] per-row margin threshold
#define SIDX     37888      // int[128]
#define SRED     38400      // float[8]
#define SM_TOTAL 38464

extern __shared__ char smx[];
__global__ __launch_bounds__(256, 4) void vq_main(
    const float* __restrict__ x, const float* __restrict__ cb,
    float* __restrict__ out)
{
    const uint32_t sbase = smem_u32(smx);
    const int tid = threadIdx.x, w = tid >> 5, lane = tid & 31;
    const int rowbase = blockIdx.x * 128;
    int*   sIdx = (int*)(smx + SIDX);
    float* sW   = (float*)(smx + SW);
    const float B2HI = __uint_as_float(g_b2hi_u);
    const float B2LO = __uint_as_float(g_b2lo_u);

    // prologue: async-load B half-tile 0 + c0 into stage 0
    {
        #pragma unroll
        for (int i = 0; i < 2; ++i) {
            int c = tid + i * 256;
            int r = c >> 3, cc = c & 7;
            cpasync16(sbase + SB + r * ASTRIDE + cc * 16,
                      (const char*)g_bpk + ((size_t)r * DIM + cc * 8) * 2);
        }
        if (tid < 16)
            cpasync16(sbase + SC0 + tid * 16, (const char*)g_c0 + tid * 16);
        asm volatile("cp.async.commit_group;" ::: "memory");
    }

    // ---- A tile: x -> bf16 hi into smem; norms -> per-row margin W ----
    {
        const float4* gx = (const float4*)(x + (size_t)rowbase * DIM);
        #pragma unroll
        for (int i = 0; i < 8; ++i) {
            int e = tid + i * 256;
            int r = e >> 4, c = (e & 15) << 2;
            float4 v = gx[e];
            __nv_bfloat162 h0, h1;
            h0.x = __float2bfloat16(v.x); h0.y = __float2bfloat16(v.y);
            h1.x = __float2bfloat16(v.z); h1.y = __float2bfloat16(v.w);
            float f0 = __bfloat162float(h0.x), f1 = __bfloat162float(h0.y);
            float f2 = __bfloat162float(h1.x), f3 = __bfloat162float(h1.y);
            float hi2 = f0 * f0 + f1 * f1 + f2 * f2 + f3 * f3;
            float l0 = v.x - f0, l1 = v.y - f1, l2 = v.z - f2, l3 = v.w - f3;
            float lo2 = l0 * l0 + l1 * l1 + l2 * l2 + l3 * l3;
            uint2 pk;
            pk.x = *(uint32_t*)&h0; pk.y = *(uint32_t*)&h1;
            *(uint2*)(smx + SA + r * ASTRIDE + c * 2) = pk;
            #pragma unroll
            for (int m = 1; m < 16; m <<= 1) {
                hi2 += __shfl_xor_sync(0xffffffffu, hi2, m);
                lo2 += __shfl_xor_sync(0xffffffffu, lo2, m);
            }
            if ((tid & 15) == 0)
                sW[r] = C1_MARG + 2.0f * (sqrtf(hi2) * B2LO
                                          + sqrtf(lo2) * (B2HI + B2LO));
        }
    }

    const uint32_t aAddr = sbase + SA + (w * 16 + (lane & 15)) * ASTRIDE + ((lane >> 4) << 4);
    const uint32_t bAddr0 = sbase + SB +
        ((lane & 7) + ((lane >> 3) & 1) * 8) * ASTRIDE + ((lane >> 4) << 4);

    uint32_t t1[2] = {~0u, ~0u}, t2[2] = {~0u, ~0u};
    int th[2] = {0, 0};
    const uint32_t KC = 0x60000000u + 2 * (lane & 3);  // folds -(SBASE*64) mod 2^32

    for (int h = 0; h < 16; ++h) {
        asm volatile("cp.async.wait_group 0;" ::: "memory");
        __syncthreads();   // B(h)+c0(h) ready; compute on other stage done
        if (h < 15) {
            int st = (h + 1) & 1;
            #pragma unroll
            for (int i = 0; i < 2; ++i) {
                int c = tid + i * 256;
                int r = c >> 3, cc = c & 7;
                cpasync16(sbase + SB + st * SBSTG + r * ASTRIDE + cc * 16,
                          (const char*)g_bpk +
                          ((size_t)((h + 1) * 64 + r) * DIM + cc * 8) * 2);
            }
            if (tid < 16)
                cpasync16(sbase + SC0 + st * 256 + tid * 16,
                          (const char*)(g_c0 + (h + 1) * 64) + tid * 16);
            asm volatile("cp.async.commit_group;" ::: "memory");
        }

        const uint32_t bAddr = bAddr0 + (h & 1) * SBSTG;
        float d[8][4];
        #pragma unroll
        for (int nb = 0; nb < 8; ++nb)
            #pragma unroll
            for (int j = 0; j < 4; ++j) d[nb][j] = 0.0f;

        #pragma unroll
        for (int s = 0; s < 4; ++s) {
            uint32_t a0[4];
            ldsm4(a0, aAddr + 32 * s);
            #pragma unroll
            for (int nbp = 0; nbp < 4; ++nbp) {
                uint32_t bb[4];
                ldsm4(bb, bAddr + nbp * 16 * ASTRIDE + 32 * s);
                mma_bf16(d[2 * nbp],     a0, bb[0], bb[2]);
                mma_bf16(d[2 * nbp + 1], a0, bb[1], bb[3]);
            }
        }

        // epilogue: score = d + c0 (fp32), lossless (score,col) key, min1/min2
        const float* c0s = (const float*)(smx + SC0 + (h & 1) * 256);
        uint32_t p0 = t1[0], p1 = t1[1];
        #pragma unroll
        for (int nb = 0; nb < 8; ++nb) {
            float2 cc = *(const float2*)(c0s + nb * 8 + 2 * (lane & 3));
            #pragma unroll
            for (int j = 0; j < 4; ++j) {
                float sc = d[nb][j] + ((j & 1) ? cc.y : cc.x);
                sc = fminf(fmaxf(sc, 0.25f), 0.75f);   // binding -> margin 0 -> flag
                uint32_t key = __float_as_uint(sc) * 64u + KC
                             + (uint32_t)(nb * 8 + (j & 1));
                int sl = j >> 1;
                t2[sl] = min(t2[sl], max(t1[sl], key));
                t1[sl] = min(t1[sl], key);
            }
        }
        if (t1[0] != p0) th[0] = h;
        if (t1[1] != p1) th[1] = h;
    }

    // merge across the 4 col-lanes (ties always flag -> order moot)
    #pragma unroll
    for (int m = 1; m <= 2; m <<= 1) {
        #pragma unroll
        for (int sl = 0; sl < 2; ++sl) {
            uint32_t o1 = __shfl_xor_sync(~0u, t1[sl], m);
            int      ot = __shfl_xor_sync(~0u, th[sl], m);
            uint32_t o2 = __shfl_xor_sync(~0u, t2[sl], m);
            uint32_t n2 = min(min(t2[sl], o2), max(t1[sl], o1));
            if (o1 < t1[sl]) { t1[sl] = o1; th[sl] = ot; }
            t2[sl] = n2;
        }
    }
    if ((lane & 3) == 0) {
        #pragma unroll
        for (int sl = 0; sl < 2; ++sl) {
            int row = w * 16 + (lane >> 2) + sl * 8;
            int k = th[sl] * 64 + (int)(t1[sl] & 63u);
            float s1 = __uint_as_float(SBASE + (t1[sl] >> 6));
            float s2 = __uint_as_float(SBASE + (t2[sl] >> 6));
            bool fl = (s2 - s1) < sW[row];
            sIdx[row] = fl ? -1 : k;
            if (fl) g_flag[atomicAdd(&g_nflag, 1)] = rowbase + row;
        }
    }
    __syncthreads();

    // fused output + loss for unflagged rows
    float lsum = 0.0f;
    #pragma unroll
    for (int i = 0; i < 8; ++i) {
        int e = tid + i * 256;
        int r = e >> 4, d4 = (e & 15) * 4;
        int k = sIdx[r];
        if (k >= 0) {
            float4 q  = __ldg((const float4*)(cb + (size_t)k * DIM + d4));
            float4 xv = __ldg((const float4*)(x + (size_t)(rowbase + r) * DIM + d4));
            *(float4*)(out + (size_t)(rowbase + r) * DIM + d4) = q;
            float a = q.x - xv.x, b = q.y - xv.y, c = q.z - xv.z, dd = q.w - xv.w;
            lsum += a * a + b * b + c * c + dd * dd;
        }
    }
    #pragma unroll
    for (int m = 16; m >= 1; m >>= 1)
        lsum += __shfl_xor_sync(0xffffffffu, lsum, m);
    float* sRed = (float*)(smx + SRED);
    if (lane == 0) sRed[w] = lsum;
    __syncthreads();
    if (tid < 8) {
        float v = sRed[tid];
        #pragma unroll
        for (int m = 4; m >= 1; m >>= 1)
            v += __shfl_xor_sync(0x000000ffu, v, m);
        if (tid == 0) atomicAdd(&g_loss, v);
    }
}

// ==== stage 2: exact bit-matched rescan of flagged rows + output + finish ====
__global__ __launch_bounds__(256) void vq_fix(const float* __restrict__ x,
                                              const float* __restrict__ cb,
                                              float* __restrict__ out,
                                              int pos, float inv_n) {
    __shared__ float sX[16 * 65];
    __shared__ float sE[128 * 65];
    __shared__ float sH[128];
    __shared__ float sXn[16];
    __shared__ int   sRow[16];
    __shared__ float sRed[8];
    const int tid = threadIdx.x, tx = tid & 15, ty = tid >> 4;
    const int nf = g_nflag;
    float lsum = 0.0f;

    for (int base = blockIdx.x * 16; base < nf; base += gridDim.x * 16) {
        int cnt = min(16, nf - base);
        __syncthreads();
        if (tid < 16) sRow[tid] = g_flag[base + min(tid, cnt - 1)];
        __syncthreads();
        {
            int r = tid >> 4, d = (tid & 15) * 4;
            float4 v = *(const float4*)(x + (size_t)sRow[r] * DIM + d);
            float* p = sX + r * 65 + d;
            p[0] = v.x; p[1] = v.y; p[2] = v.z; p[3] = v.w;
        }
        __syncthreads();
        if (tid < 16) {
            const float* p = sX + tid * 65;
            float s = 0.0f;
            #pragma unroll
            for (int i = 0; i < DIM; ++i)
                s = __fadd_rn(s, __fmul_rn(p[i], p[i]));
            sXn[tid] = s;
        }
        float bestv = 3.4e38f; int besti = 0;
        for (int t = 0; t < 8; ++t) {
            __syncthreads();
            #pragma unroll
            for (int i = 0; i < 8; ++i) {
                int e = tid + i * 256;
                int c = e >> 4, d = (e & 15) * 4;
                float4 v = *(const float4*)(cb + (size_t)(t * 128 + c) * DIM + d);
                float* p = sE + c * 65 + d;
                p[0] = v.x; p[1] = v.y; p[2] = v.z; p[3] = v.w;
            }
            if (tid < 128) sH[tid] = g_e[t * 128 + tid];
            __syncthreads();
            float acc[8];
            #pragma unroll
            for (int j = 0; j < 8; ++j) acc[j] = 0.0f;
            #pragma unroll 4
            for (int d = 0; d < DIM; ++d) {
                float xv = sX[ty * 65 + d];
                #pragma unroll
                for (int j = 0; j < 8; ++j) acc[j] += xv * sE[(tx + 16 * j) * 65 + d];
            }
            #pragma unroll
            for (int j = 0; j < 8; ++j) {
                int cg = tx + 16 * j;
                float dist = __fsub_rn(__fadd_rn(sXn[ty], sH[cg]),
                                       __fmul_rn(2.0f, acc[j]));
                if (dist < bestv) { bestv = dist; besti = t * 128 + cg; }
            }
        }
        #pragma unroll
        for (int m = 1; m < 16; m <<= 1) {
            float ov = __shfl_xor_sync(0xffffffffu, bestv, m);
            int   oi = __shfl_xor_sync(0xffffffffu, besti, m);
            if (ov < bestv || (ov == bestv && oi < besti)) { bestv = ov; besti = oi; }
        }
        if (ty < cnt) {
            int d = tx * 4;
            float4 q = __ldg((const float4*)(cb + (size_t)besti * DIM + d));
            *(float4*)(out + (size_t)sRow[ty] * DIM + d) = q;
            const float* xp = sX + ty * 65 + d;
            float a = q.x - xp[0], b = q.y - xp[1], c = q.z - xp[2], dd = q.w - xp[3];
            lsum += a * a + b * b + c * c + dd * dd;
        }
    }
    #pragma unroll
    for (int m = 16; m >= 1; m >>= 1)
        lsum += __shfl_xor_sync(0xffffffffu, lsum, m);
    __syncthreads();
    if ((tid & 31) == 0) sRed[tid >> 5] = lsum;
    __syncthreads();
    if (tid < 8) {
        float v = sRed[tid];
        #pragma unroll
        for (int m = 4; m >= 1; m >>= 1)
            v += __shfl_xor_sync(0x000000ffu, v, m);
        if (tid == 0) {
            atomicAdd(&g_loss, v);
            __threadfence();
            if (atomicAdd(&g_done, 1) == (int)gridDim.x - 1) {
                float total = atomicAdd(&g_loss, 0.0f);
                out[pos] = 1.25f * total * inv_n;
            }
        }
    }
}

extern "C" void kernel_launch(void* const* d_in, const int* in_sizes, int n_in,
                              void* d_out, int out_size) {
    const float* x  = (const float*)d_in[0];
    const float* cb = (const float*)d_in[1];
    float* out = (float*)d_out;
    const int nrows = in_sizes[0] / DIM;       // 65536
    const int nblocks = nrows / 128;           // 512

    cudaFuncSetAttribute(vq_main, cudaFuncAttributeMaxDynamicSharedMemorySize,
                         SM_TOTAL);

    vq_prep<<<8, 128>>>(cb);
    vq_main<<<nblocks, 256, SM_TOTAL>>>(x, cb, out);
    vq_fix<<<256, 256>>>(x, cb, out, out_size - 1,
                         1.0f / (float)((size_t)nrows * DIM));
}

// round 16
// speedup vs baseline: 1.0880x; 1.0880x over previous
#include <cuda_runtime.h>
#include <cuda_bf16.h>
#include <cstdint>

#define KCODES   1024
#define DIM      64
#define C1_MARG  8e-5f
#define SBASE    0x3E800000u     // bits of 0.25f

// ---------- device scratch (static, no allocation) ----------
__device__ float g_e[KCODES];                        // exact ref-chain enorms
__device__ __align__(16) float g_c0[KCODES];         // 0.5 + enorm
__device__ __align__(16) __nv_bfloat16 g_bpk[KCODES * DIM]; // (-2e) bf16 hi
__device__ unsigned g_b2hi_u;   // max_k ||(-2e)_hi||  (monotone, replay-idempotent)
__device__ unsigned g_b2lo_u;   // max_k ||(-2e)_lo||
__device__ int   g_flag[65536];
__device__ int   g_nflag;
__device__ int   g_done;
__device__ float g_loss;

__device__ __forceinline__ uint32_t smem_u32(const void* p) {
    uint32_t a;
    asm("{ .reg .u64 t; cvta.to.shared.u64 t, %1; cvt.u32.u64 %0, t; }"
        : "=r"(a) : "l"(p));
    return a;
}
__device__ __forceinline__ void ldsm4(uint32_t* r, uint32_t a) {
    asm volatile("ldmatrix.sync.aligned.m8n8.x4.shared.b16 {%0,%1,%2,%3}, [%4];"
        : "=r"(r[0]), "=r"(r[1]), "=r"(r[2]), "=r"(r[3]) : "r"(a));
}
__device__ __forceinline__ void mma_bf16(float* d, const uint32_t* a,
                                         uint32_t b0, uint32_t b1) {
    asm volatile(
        "mma.sync.aligned.m16n8k16.row.col.f32.bf16.bf16.f32 "
        "{%0,%1,%2,%3}, {%4,%5,%6,%7}, {%8,%9}, {%0,%1,%2,%3};"
        : "+f"(d[0]), "+f"(d[1]), "+f"(d[2]), "+f"(d[3])
        : "r"(a[0]), "r"(a[1]), "r"(a[2]), "r"(a[3]), "r"(b0), "r"(b1));
}
__device__ __forceinline__ void cpasync16(uint32_t sdst, const void* gsrc) {
    asm volatile("cp.async.cg.shared.global [%0], [%1], 16;"
                 :: "r"(sdst), "l"(gsrc) : "memory");
}

// ============ prep: exact enorm chain + bf16 B + norm bounds ============
__global__ void vq_prep(const float* __restrict__ cb) {
    int k = blockIdx.x * 128 + threadIdx.x;
    if (k == 0) { g_loss = 0.0f; g_nflag = 0; g_done = 0; }
    if (k < KCODES) {
        const float4* p4 = (const float4*)(cb + k * DIM);
        __nv_bfloat16* row = g_bpk + k * DIM;
        float s = 0.0f, h2 = 0.0f, l2 = 0.0f;
        #pragma unroll
        for (int q = 0; q < 16; ++q) {
            float4 v = p4[q];
            float e0 = v.x, e1 = v.y, e2 = v.z, e3 = v.w;
            s = __fadd_rn(s, __fmul_rn(e0, e0));
            s = __fadd_rn(s, __fmul_rn(e1, e1));
            s = __fadd_rn(s, __fmul_rn(e2, e2));
            s = __fadd_rn(s, __fmul_rn(e3, e3));
            float m0 = -2.0f * e0, m1 = -2.0f * e1, m2 = -2.0f * e2, m3 = -2.0f * e3;
            __nv_bfloat162 h01, h23;
            h01.x = __float2bfloat16(m0); h01.y = __float2bfloat16(m1);
            h23.x = __float2bfloat16(m2); h23.y = __float2bfloat16(m3);
            float f0 = __bfloat162float(h01.x), f1 = __bfloat162float(h01.y);
            float f2 = __bfloat162float(h23.x), f3 = __bfloat162float(h23.y);
            h2 += f0 * f0 + f1 * f1 + f2 * f2 + f3 * f3;
            float l0 = m0 - f0, l1 = m1 - f1, l2v = m2 - f2, l3 = m3 - f3;
            l2 += l0 * l0 + l1 * l1 + l2v * l2v + l3 * l3;
            *(__nv_bfloat162*)(row + q * 4)     = h01;
            *(__nv_bfloat162*)(row + q * 4 + 2) = h23;
        }
        g_e[k] = s;
        g_c0[k] = 0.5f + s;
        atomicMax(&g_b2hi_u, __float_as_uint(sqrtf(h2)));
        atomicMax(&g_b2lo_u, __float_as_uint(sqrtf(l2)));
    }
}

// ============ stage 1: 4-step HMMA + dynamic margin + fused output ============
#define ASTRIDE  144        // 9x16B rows -> conflict-free ldmatrix
#define SA       0          // 128*144 = 18432
#define SB       18432      // 2 stages x 64*144 = 9216
#define SBSTG    9216
#define SC0      36864      // 2 stages x 64 floats
#define SW       37376      // float[128] per-row margin threshold
#define SIDX     37888      // int[128]
#define SRED     38400      // float[8]
#define SM_TOTAL 38464

extern __shared__ char smx[];
__global__ __launch_bounds__(256, 2) void vq_main(
    const float* __restrict__ x, const float* __restrict__ cb,
    float* __restrict__ out)
{
    const uint32_t sbase = smem_u32(smx);
    const int tid = threadIdx.x, w = tid >> 5, lane = tid & 31;
    const int rowbase = blockIdx.x * 128;
    int*   sIdx = (int*)(smx + SIDX);
    float* sW   = (float*)(smx + SW);
    const float B2HI = __uint_as_float(g_b2hi_u);
    const float B2LO = __uint_as_float(g_b2lo_u);

    // prologue: async-load B half-tile 0 + c0 into stage 0
    {
        #pragma unroll
        for (int i = 0; i < 2; ++i) {
            int c = tid + i * 256;
            int r = c >> 3, cc = c & 7;
            cpasync16(sbase + SB + r * ASTRIDE + cc * 16,
                      (const char*)g_bpk + ((size_t)r * DIM + cc * 8) * 2);
        }
        if (tid < 16)
            cpasync16(sbase + SC0 + tid * 16, (const char*)g_c0 + tid * 16);
        asm volatile("cp.async.commit_group;" ::: "memory");
    }

    // ---- A tile: x -> bf16 hi into smem; norms -> per-row margin W ----
    {
        const float4* gx = (const float4*)(x + (size_t)rowbase * DIM);
        #pragma unroll
        for (int i = 0; i < 8; ++i) {
            int e = tid + i * 256;
            int r = e >> 4, c = (e & 15) << 2;
            float4 v = gx[e];
            __nv_bfloat162 h0, h1;
            h0.x = __float2bfloat16(v.x); h0.y = __float2bfloat16(v.y);
            h1.x = __float2bfloat16(v.z); h1.y = __float2bfloat16(v.w);
            float f0 = __bfloat162float(h0.x), f1 = __bfloat162float(h0.y);
            float f2 = __bfloat162float(h1.x), f3 = __bfloat162float(h1.y);
            float hi2 = f0 * f0 + f1 * f1 + f2 * f2 + f3 * f3;
            float l0 = v.x - f0, l1 = v.y - f1, l2 = v.z - f2, l3 = v.w - f3;
            float lo2 = l0 * l0 + l1 * l1 + l2 * l2 + l3 * l3;
            uint2 pk;
            pk.x = *(uint32_t*)&h0; pk.y = *(uint32_t*)&h1;
            *(uint2*)(smx + SA + r * ASTRIDE + c * 2) = pk;
            #pragma unroll
            for (int m = 1; m < 16; m <<= 1) {
                hi2 += __shfl_xor_sync(0xffffffffu, hi2, m);
                lo2 += __shfl_xor_sync(0xffffffffu, lo2, m);
            }
            if ((tid & 15) == 0)
                sW[r] = C1_MARG + 2.0f * (sqrtf(hi2) * B2LO
                                          + sqrtf(lo2) * (B2HI + B2LO));
        }
    }

    const uint32_t aAddr = sbase + SA + (w * 16 + (lane & 15)) * ASTRIDE + ((lane >> 4) << 4);
    const uint32_t bAddr0 = sbase + SB +
        ((lane & 7) + ((lane >> 3) & 1) * 8) * ASTRIDE + ((lane >> 4) << 4);

    uint32_t t1[2] = {~0u, ~0u}, t2[2] = {~0u, ~0u};
    int th[2] = {0, 0};
    const uint32_t KC = 0x60000000u + 2 * (lane & 3);  // folds -(SBASE*64) mod 2^32

    for (int h = 0; h < 16; ++h) {
        asm volatile("cp.async.wait_group 0;" ::: "memory");
        __syncthreads();   // B(h)+c0(h) ready; compute on other stage done
        if (h < 15) {
            int st = (h + 1) & 1;
            #pragma unroll
            for (int i = 0; i < 2; ++i) {
                int c = tid + i * 256;
                int r = c >> 3, cc = c & 7;
                cpasync16(sbase + SB + st * SBSTG + r * ASTRIDE + cc * 16,
                          (const char*)g_bpk +
                          ((size_t)((h + 1) * 64 + r) * DIM + cc * 8) * 2);
            }
            if (tid < 16)
                cpasync16(sbase + SC0 + st * 256 + tid * 16,
                          (const char*)(g_c0 + (h + 1) * 64) + tid * 16);
            asm volatile("cp.async.commit_group;" ::: "memory");
        }

        const uint32_t bAddr = bAddr0 + (h & 1) * SBSTG;
        float d[8][4];
        #pragma unroll
        for (int nb = 0; nb < 8; ++nb)
            #pragma unroll
            for (int j = 0; j < 4; ++j) d[nb][j] = 0.0f;

        #pragma unroll
        for (int s = 0; s < 4; ++s) {
            uint32_t a0[4];
            ldsm4(a0, aAddr + 32 * s);
            #pragma unroll
            for (int nbp = 0; nbp < 4; ++nbp) {
                uint32_t bb[4];
                ldsm4(bb, bAddr + nbp * 16 * ASTRIDE + 32 * s);
                mma_bf16(d[2 * nbp],     a0, bb[0], bb[2]);
                mma_bf16(d[2 * nbp + 1], a0, bb[1], bb[3]);
            }
        }

        // epilogue: score = d + c0 (fp32), lossless (score,col) key, min1/min2
        const float* c0s = (const float*)(smx + SC0 + (h & 1) * 256);
        uint32_t p0 = t1[0], p1 = t1[1];
        #pragma unroll
        for (int nb = 0; nb < 8; ++nb) {
            float2 cc = *(const float2*)(c0s + nb * 8 + 2 * (lane & 3));
            #pragma unroll
            for (int j = 0; j < 4; ++j) {
                float sc = d[nb][j] + ((j & 1) ? cc.y : cc.x);
                sc = fminf(fmaxf(sc, 0.25f), 0.75f);   // binding -> margin 0 -> flag
                uint32_t key = __float_as_uint(sc) * 64u + KC
                             + (uint32_t)(nb * 8 + (j & 1));
                int sl = j >> 1;
                t2[sl] = min(t2[sl], max(t1[sl], key));
                t1[sl] = min(t1[sl], key);
            }
        }
        if (t1[0] != p0) th[0] = h;
        if (t1[1] != p1) th[1] = h;
    }

    // merge across the 4 col-lanes (ties always flag -> order moot)
    #pragma unroll
    for (int m = 1; m <= 2; m <<= 1) {
        #pragma unroll
        for (int sl = 0; sl < 2; ++sl) {
            uint32_t o1 = __shfl_xor_sync(~0u, t1[sl], m);
            int      ot = __shfl_xor_sync(~0u, th[sl], m);
            uint32_t o2 = __shfl_xor_sync(~0u, t2[sl], m);
            uint32_t n2 = min(min(t2[sl], o2), max(t1[sl], o1));
            if (o1 < t1[sl]) { t1[sl] = o1; th[sl] = ot; }
            t2[sl] = n2;
        }
    }
    if ((lane & 3) == 0) {
        #pragma unroll
        for (int sl = 0; sl < 2; ++sl) {
            int row = w * 16 + (lane >> 2) + sl * 8;
            int k = th[sl] * 64 + (int)(t1[sl] & 63u);
            float s1 = __uint_as_float(SBASE + (t1[sl] >> 6));
            float s2 = __uint_as_float(SBASE + (t2[sl] >> 6));
            bool fl = (s2 - s1) < sW[row];
            sIdx[row] = fl ? -1 : k;
            if (fl) g_flag[atomicAdd(&g_nflag, 1)] = rowbase + row;
        }
    }
    __syncthreads();

    // fused output + loss for unflagged rows
    float lsum = 0.0f;
    #pragma unroll
    for (int i = 0; i < 8; ++i) {
        int e = tid + i * 256;
        int r = e >> 4, d4 = (e & 15) * 4;
        int k = sIdx[r];
        if (k >= 0) {
            float4 q  = __ldg((const float4*)(cb + (size_t)k * DIM + d4));
            float4 xv = __ldg((const float4*)(x + (size_t)(rowbase + r) * DIM + d4));
            *(float4*)(out + (size_t)(rowbase + r) * DIM + d4) = q;
            float a = q.x - xv.x, b = q.y - xv.y, c = q.z - xv.z, dd = q.w - xv.w;
            lsum += a * a + b * b + c * c + dd * dd;
        }
    }
    #pragma unroll
    for (int m = 16; m >= 1; m >>= 1)
        lsum += __shfl_xor_sync(0xffffffffu, lsum, m);
    float* sRed = (float*)(smx + SRED);
    if (lane == 0) sRed[w] = lsum;
    __syncthreads();
    if (tid < 8) {
        float v = sRed[tid];
        #pragma unroll
        for (int m = 4; m >= 1; m >>= 1)
            v += __shfl_xor_sync(0x000000ffu, v, m);
        if (tid == 0) atomicAdd(&g_loss, v);
    }
}

// ==== stage 2: exact bit-matched rescan of flagged rows + output + finish ====
__global__ __launch_bounds__(256) void vq_fix(const float* __restrict__ x,
                                              const float* __restrict__ cb,
                                              float* __restrict__ out,
                                              int pos, float inv_n) {
    __shared__ float sX[16 * 65];
    __shared__ float sE[128 * 65];
    __shared__ float sH[128];
    __shared__ float sXn[16];
    __shared__ int   sRow[16];
    __shared__ float sRed[8];
    const int tid = threadIdx.x, tx = tid & 15, ty = tid >> 4;
    const int nf = g_nflag;
    float lsum = 0.0f;

    for (int base = blockIdx.x * 16; base < nf; base += gridDim.x * 16) {
        int cnt = min(16, nf - base);
        __syncthreads();
        if (tid < 16) sRow[tid] = g_flag[base + min(tid, cnt - 1)];
        __syncthreads();
        {
            int r = tid >> 4, d = (tid & 15) * 4;
            float4 v = *(const float4*)(x + (size_t)sRow[r] * DIM + d);
            float* p = sX + r * 65 + d;
            p[0] = v.x; p[1] = v.y; p[2] = v.z; p[3] = v.w;
        }
        __syncthreads();
        if (tid < 16) {
            const float* p = sX + tid * 65;
            float s = 0.0f;
            #pragma unroll
            for (int i = 0; i < DIM; ++i)
                s = __fadd_rn(s, __fmul_rn(p[i], p[i]));
            sXn[tid] = s;
        }
        float bestv = 3.4e38f; int besti = 0;
        for (int t = 0; t < 8; ++t) {
            __syncthreads();
            #pragma unroll
            for (int i = 0; i < 8; ++i) {
                int e = tid + i * 256;
                int c = e >> 4, d = (e & 15) * 4;
                float4 v = *(const float4*)(cb + (size_t)(t * 128 + c) * DIM + d);
                float* p = sE + c * 65 + d;
                p[0] = v.x; p[1] = v.y; p[2] = v.z; p[3] = v.w;
            }
            if (tid < 128) sH[tid] = g_e[t * 128 + tid];
            __syncthreads();
            float acc[8];
            #pragma unroll
            for (int j = 0; j < 8; ++j) acc[j] = 0.0f;
            #pragma unroll 4
            for (int d = 0; d < DIM; ++d) {
                float xv = sX[ty * 65 + d];
                #pragma unroll
                for (int j = 0; j < 8; ++j) acc[j] += xv * sE[(tx + 16 * j) * 65 + d];
            }
            #pragma unroll
            for (int j = 0; j < 8; ++j) {
                int cg = tx + 16 * j;
                float dist = __fsub_rn(__fadd_rn(sXn[ty], sH[cg]),
                                       __fmul_rn(2.0f, acc[j]));
                if (dist < bestv) { bestv = dist; besti = t * 128 + cg; }
            }
        }
        #pragma unroll
        for (int m = 1; m < 16; m <<= 1) {
            float ov = __shfl_xor_sync(0xffffffffu, bestv, m);
            int   oi = __shfl_xor_sync(0xffffffffu, besti, m);
            if (ov < bestv || (ov == bestv && oi < besti)) { bestv = ov; besti = oi; }
        }
        if (ty < cnt) {
            int d = tx * 4;
            float4 q = __ldg((const float4*)(cb + (size_t)besti * DIM + d));
            *(float4*)(out + (size_t)sRow[ty] * DIM + d) = q;
            const float* xp = sX + ty * 65 + d;
            float a = q.x - xp[0], b = q.y - xp[1], c = q.z - xp[2], dd = q.w - xp[3];
            lsum += a * a + b * b + c * c + dd * dd;
        }
    }
    #pragma unroll
    for (int m = 16; m >= 1; m >>= 1)
        lsum += __shfl_xor_sync(0xffffffffu, lsum, m);
    __syncthreads();
    if ((tid & 31) == 0) sRed[tid >> 5] = lsum;
    __syncthreads();
    if (tid < 8) {
        float v = sRed[tid];
        #pragma unroll
        for (int m = 4; m >= 1; m >>= 1)
            v += __shfl_xor_sync(0x000000ffu, v, m);
        if (tid == 0) {
            atomicAdd(&g_loss, v);
            __threadfence();
            if (atomicAdd(&g_done, 1) == (int)gridDim.x - 1) {
                float total = atomicAdd(&g_loss, 0.0f);
                out[pos] = 1.25f * total * inv_n;
            }
        }
    }
}

extern "C" void kernel_launch(void* const* d_in, const int* in_sizes, int n_in,
                              void* d_out, int out_size) {
    const float* x  = (const float*)d_in[0];
    const float* cb = (const float*)d_in[1];
    float* out = (float*)d_out;
    const int nrows = in_sizes[0] / DIM;       // 65536
    const int nblocks = nrows / 128;           // 512

    cudaFuncSetAttribute(vq_main, cudaFuncAttributeMaxDynamicSharedMemorySize,
                         SM_TOTAL);

    vq_prep<<<8, 128>>>(cb);
    vq_main<<<nblocks, 256, SM_TOTAL>>>(x, cb, out);
    vq_fix<<<512, 256>>>(x, cb, out, out_size - 1,
                         1.0f / (float)((size_t)nrows * DIM));
}

// round 17
// speedup vs baseline: 2.0917x; 1.9225x over previous
#include <cuda_runtime.h>
#include <cuda_fp16.h>
#include <cstdint>

#define KCODES   1024
#define DIM      64
#define C1S      0.0103f         // 4e-5 * 256 (scaled-score constant margin)
#define SBASE    0x42800000u     // bits of 64.0f
#define HMIN     6.1035156e-5f   // fp16 min normal

// ---------- device scratch (static, no allocation) ----------
__device__ float g_e[KCODES];                        // exact ref-chain enorms
__device__ __align__(16) float g_c0[KCODES];         // 128 + 256*enorm (scaled)
__device__ __align__(16) __half g_bpk[KCODES * DIM]; // (-512e) fp16, subnorm-flushed
__device__ unsigned g_b2hi_u;   // max_k ||(-512e)_hi||  (monotone, replay-idempotent)
__device__ unsigned g_b2lo_u;   // max_k ||(-512e)_lo||
__device__ int   g_flag[65536];
__device__ int   g_nflag;
__device__ int   g_done;
__device__ float g_loss;

__device__ __forceinline__ uint32_t smem_u32(const void* p) {
    uint32_t a;
    asm("{ .reg .u64 t; cvta.to.shared.u64 t, %1; cvt.u32.u64 %0, t; }"
        : "=r"(a) : "l"(p));
    return a;
}
__device__ __forceinline__ void ldsm4(uint32_t* r, uint32_t a) {
    asm volatile("ldmatrix.sync.aligned.m8n8.x4.shared.b16 {%0,%1,%2,%3}, [%4];"
        : "=r"(r[0]), "=r"(r[1]), "=r"(r[2]), "=r"(r[3]) : "r"(a));
}
__device__ __forceinline__ void mma_f16(float* d, const uint32_t* a,
                                        uint32_t b0, uint32_t b1) {
    asm volatile(
        "mma.sync.aligned.m16n8k16.row.col.f32.f16.f16.f32 "
        "{%0,%1,%2,%3}, {%4,%5,%6,%7}, {%8,%9}, {%0,%1,%2,%3};"
        : "+f"(d[0]), "+f"(d[1]), "+f"(d[2]), "+f"(d[3])
        : "r"(a[0]), "r"(a[1]), "r"(a[2]), "r"(a[3]), "r"(b0), "r"(b1));
}
__device__ __forceinline__ void cpasync16(uint32_t sdst, const void* gsrc) {
    asm volatile("cp.async.cg.shared.global [%0], [%1], 16;"
                 :: "r"(sdst), "l"(gsrc) : "memory");
}
// fp16 convert with manual subnormal flush; returns half, outputs exact float value seen by MMA
__device__ __forceinline__ __half h_flush(float v, float& f) {
    __half h = __float2half_rn(v);
    f = __half2float(h);
    if (fabsf(f) < HMIN) { h = __ushort_as_half((unsigned short)0); f = 0.0f; }
    return h;
}

// ============ prep: exact enorm chain + fp16 B (x256 scale) + norm bounds ============
__global__ void vq_prep(const float* __restrict__ cb) {
    int k = blockIdx.x * 128 + threadIdx.x;
    if (k == 0) { g_loss = 0.0f; g_nflag = 0; g_done = 0; }
    if (k < KCODES) {
        const float4* p4 = (const float4*)(cb + k * DIM);
        __half* row = g_bpk + k * DIM;
        float s = 0.0f, h2 = 0.0f, l2 = 0.0f;
        #pragma unroll
        for (int q = 0; q < 16; ++q) {
            float4 v = p4[q];
            float e0 = v.x, e1 = v.y, e2 = v.z, e3 = v.w;
            s = __fadd_rn(s, __fmul_rn(e0, e0));
            s = __fadd_rn(s, __fmul_rn(e1, e1));
            s = __fadd_rn(s, __fmul_rn(e2, e2));
            s = __fadd_rn(s, __fmul_rn(e3, e3));
            float m0 = -512.0f * e0, m1 = -512.0f * e1;
            float m2 = -512.0f * e2, m3 = -512.0f * e3;
            float f0, f1, f2, f3;
            __half ha = h_flush(m0, f0), hb = h_flush(m1, f1);
            __half hc = h_flush(m2, f2), hd = h_flush(m3, f3);
            h2 += f0 * f0 + f1 * f1 + f2 * f2 + f3 * f3;
            float l0 = m0 - f0, l1 = m1 - f1, l2v = m2 - f2, l3 = m3 - f3;
            l2 += l0 * l0 + l1 * l1 + l2v * l2v + l3 * l3;
            row[q * 4 + 0] = ha; row[q * 4 + 1] = hb;
            row[q * 4 + 2] = hc; row[q * 4 + 3] = hd;
        }
        g_e[k] = s;
        g_c0[k] = fmaf(256.0f, s, 128.0f);   // 256*(0.5+enorm)
        atomicMax(&g_b2hi_u, __float_as_uint(sqrtf(h2)));
        atomicMax(&g_b2lo_u, __float_as_uint(sqrtf(l2)));
    }
}

// ============ stage 1: 4-step fp16 HMMA + dynamic margin + fused output ============
#define ASTRIDE  144        // 9x16B rows -> conflict-free ldmatrix
#define SA       0          // 128*144 = 18432
#define SB       18432      // 2 stages x 64*144 = 9216
#define SBSTG    9216
#define SC0      36864      // 2 stages x 64 floats
#define SW       37376      // float[128] per-row margin threshold (scaled units)
#define SIDX     37888      // int[128]
#define SRED     38400      // float[8]
#define SM_TOTAL 38464

extern __shared__ char smx[];
__global__ __launch_bounds__(256, 2) void vq_main(
    const float* __restrict__ x, const float* __restrict__ cb,
    float* __restrict__ out)
{
    const uint32_t sbase = smem_u32(smx);
    const int tid = threadIdx.x, w = tid >> 5, lane = tid & 31;
    const int rowbase = blockIdx.x * 128;
    int*   sIdx = (int*)(smx + SIDX);
    float* sW   = (float*)(smx + SW);
    const float B2HI = __uint_as_float(g_b2hi_u);
    const float B2LO = __uint_as_float(g_b2lo_u);

    // prologue: async-load B half-tile 0 + c0 into stage 0
    {
        #pragma unroll
        for (int i = 0; i < 2; ++i) {
            int c = tid + i * 256;
            int r = c >> 3, cc = c & 7;
            cpasync16(sbase + SB + r * ASTRIDE + cc * 16,
                      (const char*)g_bpk + ((size_t)r * DIM + cc * 8) * 2);
        }
        if (tid < 16)
            cpasync16(sbase + SC0 + tid * 16, (const char*)g_c0 + tid * 16);
        asm volatile("cp.async.commit_group;" ::: "memory");
    }

    // ---- A tile: x -> fp16 (flushed) into smem; residual norms -> margin W ----
    {
        const float4* gx = (const float4*)(x + (size_t)rowbase * DIM);
        #pragma unroll
        for (int i = 0; i < 8; ++i) {
            int e = tid + i * 256;
            int r = e >> 4, c = (e & 15) << 2;
            float4 v = gx[e];
            float f0, f1, f2, f3;
            __half2 h01, h23;
            h01.x = h_flush(v.x, f0); h01.y = h_flush(v.y, f1);
            h23.x = h_flush(v.z, f2); h23.y = h_flush(v.w, f3);
            float hi2 = f0 * f0 + f1 * f1 + f2 * f2 + f3 * f3;
            float l0 = v.x - f0, l1 = v.y - f1, l2 = v.z - f2, l3 = v.w - f3;
            float lo2 = l0 * l0 + l1 * l1 + l2 * l2 + l3 * l3;
            uint2 pk;
            pk.x = *(uint32_t*)&h01; pk.y = *(uint32_t*)&h23;
            *(uint2*)(smx + SA + r * ASTRIDE + c * 2) = pk;
            #pragma unroll
            for (int m = 1; m < 16; m <<= 1) {
                hi2 += __shfl_xor_sync(0xffffffffu, hi2, m);
                lo2 += __shfl_xor_sync(0xffffffffu, lo2, m);
            }
            if ((tid & 15) == 0)
                sW[r] = C1S + 2.0f * (sqrtf(hi2) * B2LO
                                      + sqrtf(lo2) * (B2HI + B2LO));
        }
    }

    const uint32_t aAddr = sbase + SA + (w * 16 + (lane & 15)) * ASTRIDE + ((lane >> 4) << 4);
    const uint32_t bAddr0 = sbase + SB +
        ((lane & 7) + ((lane >> 3) & 1) * 8) * ASTRIDE + ((lane >> 4) << 4);

    uint32_t t1[2] = {~0u, ~0u}, t2[2] = {~0u, ~0u};
    int th[2] = {0, 0};
    const uint32_t KC = 0x60000000u + 2 * (lane & 3);  // folds -(SBASE*64) mod 2^32

    for (int h = 0; h < 16; ++h) {
        asm volatile("cp.async.wait_group 0;" ::: "memory");
        __syncthreads();   // B(h)+c0(h) ready; compute on other stage done
        if (h < 15) {
            int st = (h + 1) & 1;
            #pragma unroll
            for (int i = 0; i < 2; ++i) {
                int c = tid + i * 256;
                int r = c >> 3, cc = c & 7;
                cpasync16(sbase + SB + st * SBSTG + r * ASTRIDE + cc * 16,
                          (const char*)g_bpk +
                          ((size_t)((h + 1) * 64 + r) * DIM + cc * 8) * 2);
            }
            if (tid < 16)
                cpasync16(sbase + SC0 + st * 256 + tid * 16,
                          (const char*)(g_c0 + (h + 1) * 64) + tid * 16);
            asm volatile("cp.async.commit_group;" ::: "memory");
        }

        const uint32_t bAddr = bAddr0 + (h & 1) * SBSTG;
        float d[8][4];
        #pragma unroll
        for (int nb = 0; nb < 8; ++nb)
            #pragma unroll
            for (int j = 0; j < 4; ++j) d[nb][j] = 0.0f;

        #pragma unroll
        for (int s = 0; s < 4; ++s) {
            uint32_t a0[4];
            ldsm4(a0, aAddr + 32 * s);
            #pragma unroll
            for (int nbp = 0; nbp < 4; ++nbp) {
                uint32_t bb[4];
                ldsm4(bb, bAddr + nbp * 16 * ASTRIDE + 32 * s);
                mma_f16(d[2 * nbp],     a0, bb[0], bb[2]);
                mma_f16(d[2 * nbp + 1], a0, bb[1], bb[3]);
            }
        }

        // epilogue: score = d + c0' (scaled fp32), lossless (score,col) key, min1/min2
        const float* c0s = (const float*)(smx + SC0 + (h & 1) * 256);
        uint32_t p0 = t1[0], p1 = t1[1];
        #pragma unroll
        for (int nb = 0; nb < 8; ++nb) {
            float2 cc = *(const float2*)(c0s + nb * 8 + 2 * (lane & 3));
            #pragma unroll
            for (int j = 0; j < 4; ++j) {
                float sc = d[nb][j] + ((j & 1) ? cc.y : cc.x);
                sc = fminf(fmaxf(sc, 64.0f), 192.0f);  // binding -> margin 0 -> flag
                uint32_t key = __float_as_uint(sc) * 64u + KC
                             + (uint32_t)(nb * 8 + (j & 1));
                int sl = j >> 1;
                t2[sl] = min(t2[sl], max(t1[sl], key));
                t1[sl] = min(t1[sl], key);
            }
        }
        if (t1[0] != p0) th[0] = h;
        if (t1[1] != p1) th[1] = h;
    }

    // merge across the 4 col-lanes (ties always flag -> order moot)
    #pragma unroll
    for (int m = 1; m <= 2; m <<= 1) {
        #pragma unroll
        for (int sl = 0; sl < 2; ++sl) {
            uint32_t o1 = __shfl_xor_sync(~0u, t1[sl], m);
            int      ot = __shfl_xor_sync(~0u, th[sl], m);
            uint32_t o2 = __shfl_xor_sync(~0u, t2[sl], m);
            uint32_t n2 = min(min(t2[sl], o2), max(t1[sl], o1));
            if (o1 < t1[sl]) { t1[sl] = o1; th[sl] = ot; }
            t2[sl] = n2;
        }
    }
    if ((lane & 3) == 0) {
        #pragma unroll
        for (int sl = 0; sl < 2; ++sl) {
            int row = w * 16 + (lane >> 2) + sl * 8;
            int k = th[sl] * 64 + (int)(t1[sl] & 63u);
            float s1 = __uint_as_float(SBASE + (t1[sl] >> 6));
            float s2 = __uint_as_float(SBASE + (t2[sl] >> 6));
            bool fl = (s2 - s1) < sW[row];
            sIdx[row] = fl ? -1 : k;
            if (fl) g_flag[atomicAdd(&g_nflag, 1)] = rowbase + row;
        }
    }
    __syncthreads();

    // fused output + loss for unflagged rows
    float lsum = 0.0f;
    #pragma unroll
    for (int i = 0; i < 8; ++i) {
        int e = tid + i * 256;
        int r = e >> 4, d4 = (e & 15) * 4;
        int k = sIdx[r];
        if (k >= 0) {
            float4 q  = __ldg((const float4*)(cb + (size_t)k * DIM + d4));
            float4 xv = __ldg((const float4*)(x + (size_t)(rowbase + r) * DIM + d4));
            *(float4*)(out + (size_t)(rowbase + r) * DIM + d4) = q;
            float a = q.x - xv.x, b = q.y - xv.y, c = q.z - xv.z, dd = q.w - xv.w;
            lsum += a * a + b * b + c * c + dd * dd;
        }
    }
    #pragma unroll
    for (int m = 16; m >= 1; m >>= 1)
        lsum += __shfl_xor_sync(0xffffffffu, lsum, m);
    float* sRed = (float*)(smx + SRED);
    if (lane == 0) sRed[w] = lsum;
    __syncthreads();
    if (tid < 8) {
        float v = sRed[tid];
        #pragma unroll
        for (int m = 4; m >= 1; m >>= 1)
            v += __shfl_xor_sync(0x000000ffu, v, m);
        if (tid == 0) atomicAdd(&g_loss, v);
    }
}

// ==== stage 2: exact bit-matched rescan of flagged rows + output + finish ====
__global__ __launch_bounds__(256) void vq_fix(const float* __restrict__ x,
                                              const float* __restrict__ cb,
                                              float* __restrict__ out,
                                              int pos, float inv_n) {
    __shared__ float sX[16 * 65];
    __shared__ float sE[128 * 65];
    __shared__ float sH[128];
    __shared__ float sXn[16];
    __shared__ int   sRow[16];
    __shared__ float sRed[8];
    const int tid = threadIdx.x, tx = tid & 15, ty = tid >> 4;
    const int nf = g_nflag;
    float lsum = 0.0f;

    for (int base = blockIdx.x * 16; base < nf; base += gridDim.x * 16) {
        int cnt = min(16, nf - base);
        __syncthreads();
        if (tid < 16) sRow[tid] = g_flag[base + min(tid, cnt - 1)];
        __syncthreads();
        {
            int r = tid >> 4, d = (tid & 15) * 4;
            float4 v = *(const float4*)(x + (size_t)sRow[r] * DIM + d);
            float* p = sX + r * 65 + d;
            p[0] = v.x; p[1] = v.y; p[2] = v.z; p[3] = v.w;
        }
        __syncthreads();
        if (tid < 16) {
            const float* p = sX + tid * 65;
            float s = 0.0f;
            #pragma unroll
            for (int i = 0; i < DIM; ++i)
                s = __fadd_rn(s, __fmul_rn(p[i], p[i]));
            sXn[tid] = s;
        }
        float bestv = 3.4e38f; int besti = 0;
        for (int t = 0; t < 8; ++t) {
            __syncthreads();
            #pragma unroll
            for (int i = 0; i < 8; ++i) {
                int e = tid + i * 256;
                int c = e >> 4, d = (e & 15) * 4;
                float4 v = *(const float4*)(cb + (size_t)(t * 128 + c) * DIM + d);
                float* p = sE + c * 65 + d;
                p[0] = v.x; p[1] = v.y; p[2] = v.z; p[3] = v.w;
            }
            if (tid < 128) sH[tid] = g_e[t * 128 + tid];
            __syncthreads();
            float acc[8];
            #pragma unroll
            for (int j = 0; j < 8; ++j) acc[j] = 0.0f;
            #pragma unroll 4
            for (int d = 0; d < DIM; ++d) {
                float xv = sX[ty * 65 + d];
                #pragma unroll
                for (int j = 0; j < 8; ++j) acc[j] += xv * sE[(tx + 16 * j) * 65 + d];
            }
            #pragma unroll
            for (int j = 0; j < 8; ++j) {
                int cg = tx + 16 * j;
                float dist = __fsub_rn(__fadd_rn(sXn[ty], sH[cg]),
                                       __fmul_rn(2.0f, acc[j]));
                if (dist < bestv) { bestv = dist; besti = t * 128 + cg; }
            }
        }
        #pragma unroll
        for (int m = 1; m < 16; m <<= 1) {
            float ov = __shfl_xor_sync(0xffffffffu, bestv, m);
            int   oi = __shfl_xor_sync(0xffffffffu, besti, m);
            if (ov < bestv || (ov == bestv && oi < besti)) { bestv = ov; besti = oi; }
        }
        if (ty < cnt) {
            int d = tx * 4;
            float4 q = __ldg((const float4*)(cb + (size_t)besti * DIM + d));
            *(float4*)(out + (size_t)sRow[ty] * DIM + d) = q;
            const float* xp = sX + ty * 65 + d;
            float a = q.x - xp[0], b = q.y - xp[1], c = q.z - xp[2], dd = q.w - xp[3];
            lsum += a * a + b * b + c * c + dd * dd;
        }
    }
    #pragma unroll
    for (int m = 16; m >= 1; m >>= 1)
        lsum += __shfl_xor_sync(0xffffffffu, lsum, m);
    __syncthreads();
    if ((tid & 31) == 0) sRed[tid >> 5] = lsum;
    __syncthreads();
    if (tid < 8) {
        float v = sRed[tid];
        #pragma unroll
        for (int m = 4; m >= 1; m >>= 1)
            v += __shfl_xor_sync(0x000000ffu, v, m);
        if (tid == 0) {
            atomicAdd(&g_loss, v);
            __threadfence();
            if (atomicAdd(&g_done, 1) == (int)gridDim.x - 1) {
                float total = atomicAdd(&g_loss, 0.0f);
                out[pos] = 1.25f * total * inv_n;
            }
        }
    }
}

extern "C" void kernel_launch(void* const* d_in, const int* in_sizes, int n_in,
                              void* d_out, int out_size) {
    const float* x  = (const float*)d_in[0];
    const float* cb = (const float*)d_in[1];
    float* out = (float*)d_out;
    const int nrows = in_sizes[0] / DIM;       // 65536
    const int nblocks = nrows / 128;           // 512

    cudaFuncSetAttribute(vq_main, cudaFuncAttributeMaxDynamicSharedMemorySize,
                         SM_TOTAL);

    vq_prep<<<8, 128>>>(cb);
    vq_main<<<nblocks, 256, SM_TOTAL>>>(x, cb, out);
    vq_fix<<<512, 256>>>(x, cb, out, out_size - 1,
                         1.0f / (float)((size_t)nrows * DIM));
}